// round 3
// baseline (speedup 1.0000x reference)
#include <cuda_runtime.h>

// B=4, T=2048, C=768, H=12, D=64, 3C=2304, BH=48

__device__ float g_qkv  [4*2048*2304];   // [B,T,3C]
__device__ float g_kur  [48*2048*64];    // k @ Ur   [B*H,T,D]
__device__ float g_kun  [48*2048*64];    // k @ Un
__device__ float g_local[48*2048*64];    // attention out
__device__ float g_rnn  [48*2048*64];    // scan out
__device__ float g_alpha[4*2048*12];     // gate [B*T,H]
__device__ float g_y    [4*2048*768];    // mixed
__device__ int   g_win;

// ---- window scalar normalization (robust to int32/int64/float encodings) ---
__global__ void win_kernel(const void* wp) {
    int v = *(const int*)wp;
    if (v < 1 || v > 4096) {
        float f = *(const float*)wp;
        int vf = (int)f;
        if (vf >= 1 && vf <= 4096) v = vf; else v = 256;
    }
    g_win = v;
}

// ---- SGEMM + bias: C[M,N] = A[M,K]@B[K,N] + bias, 128x128x16, 256 thr ------
__global__ __launch_bounds__(256) void sgemm_bias(
    const float* __restrict__ A, const float* __restrict__ Bm,
    const float* __restrict__ bias, float* __restrict__ C,
    int M, int N, int K)
{
    __shared__ float As[16][132];
    __shared__ float Bs[16][128];
    const int tid = threadIdx.x;
    const int bm = blockIdx.y * 128, bn = blockIdx.x * 128;
    const int tx = tid & 15, ty = tid >> 4;

    float acc[8][8];
#pragma unroll
    for (int i = 0; i < 8; i++)
#pragma unroll
        for (int j = 0; j < 8; j++) acc[i][j] = 0.f;

    for (int k0 = 0; k0 < K; k0 += 16) {
#pragma unroll
        for (int i = 0; i < 2; i++) {
            int s = i * 256 + tid;
            int r = s >> 2, kk = (s & 3) << 2;
            float4 a = *(const float4*)(A + (size_t)(bm + r) * K + k0 + kk);
            As[kk + 0][r] = a.x; As[kk + 1][r] = a.y;
            As[kk + 2][r] = a.z; As[kk + 3][r] = a.w;
        }
#pragma unroll
        for (int i = 0; i < 2; i++) {
            int s = i * 256 + tid;
            int r = s >> 5, cc = (s & 31) << 2;
            *(float4*)(&Bs[r][cc]) = *(const float4*)(Bm + (size_t)(k0 + r) * N + bn + cc);
        }
        __syncthreads();
#pragma unroll
        for (int kk = 0; kk < 16; kk++) {
            float a[8], b[8];
            *(float4*)&a[0] = *(float4*)&As[kk][ty * 4];
            *(float4*)&a[4] = *(float4*)&As[kk][64 + ty * 4];
            *(float4*)&b[0] = *(float4*)&Bs[kk][tx * 4];
            *(float4*)&b[4] = *(float4*)&Bs[kk][64 + tx * 4];
#pragma unroll
            for (int i = 0; i < 8; i++)
#pragma unroll
                for (int j = 0; j < 8; j++)
                    acc[i][j] = fmaf(a[i], b[j], acc[i][j]);
        }
        __syncthreads();
    }
#pragma unroll
    for (int ih = 0; ih < 2; ih++)
#pragma unroll
        for (int i = 0; i < 4; i++) {
            int r = bm + ih * 64 + ty * 4 + i;
#pragma unroll
            for (int jh = 0; jh < 2; jh++) {
                int cc = bn + jh * 64 + tx * 4;
                float4 bv = *(const float4*)(bias + cc);
                float4 o;
                o.x = acc[ih * 4 + i][jh * 4 + 0] + bv.x;
                o.y = acc[ih * 4 + i][jh * 4 + 1] + bv.y;
                o.z = acc[ih * 4 + i][jh * 4 + 2] + bv.z;
                o.w = acc[ih * 4 + i][jh * 4 + 3] + bv.w;
                *(float4*)(C + (size_t)r * N + cc) = o;
            }
        }
}

// ---- kUr/kUn: per (b,h), 64-row time tiles: [64,64]@[64,64] x2 -------------
__global__ __launch_bounds__(256) void ku_kernel(
    const float* __restrict__ Ur, const float* __restrict__ Un)
{
    __shared__ float ks[64][64];
    __shared__ float ur[64][64];
    __shared__ float un[64][64];
    const int t64 = blockIdx.x, bh = blockIdx.y;
    const int b = bh / 12, h = bh - b * 12;
    const int tid = threadIdx.x;
#pragma unroll
    for (int i = 0; i < 4; i++) {
        int s = i * 256 + tid;
        ((float4*)ur)[s] = ((const float4*)Ur)[s];
        ((float4*)un)[s] = ((const float4*)Un)[s];
    }
    const float* kb = g_qkv + ((size_t)(b * 2048 + t64 * 64)) * 2304 + 768 + h * 64;
#pragma unroll
    for (int q = 0; q < 4; q++) {
        int s = q * 256 + tid;
        int r = s >> 4, d0 = (s & 15) << 2;
        *(float4*)&ks[r][d0] = *(const float4*)(kb + (size_t)r * 2304 + d0);
    }
    __syncthreads();
    const int tx = tid & 15, ty = tid >> 4;
    float ar[4][4], an[4][4];
#pragma unroll
    for (int i = 0; i < 4; i++)
#pragma unroll
        for (int j = 0; j < 4; j++) { ar[i][j] = 0.f; an[i][j] = 0.f; }

    for (int i0 = 0; i0 < 64; i0 += 4) {
        float krr[4][4];
#pragma unroll
        for (int rr = 0; rr < 4; rr++)
            *(float4*)&krr[rr][0] = *(const float4*)&ks[ty * 4 + rr][i0];
#pragma unroll
        for (int q = 0; q < 4; q++) {
            float uR[4], uN[4];
            *(float4*)&uR[0] = *(const float4*)&ur[i0 + q][tx * 4];
            *(float4*)&uN[0] = *(const float4*)&un[i0 + q][tx * 4];
#pragma unroll
            for (int rr = 0; rr < 4; rr++)
#pragma unroll
                for (int cc = 0; cc < 4; cc++) {
                    ar[rr][cc] = fmaf(krr[rr][q], uR[cc], ar[rr][cc]);
                    an[rr][cc] = fmaf(krr[rr][q], uN[cc], an[rr][cc]);
                }
        }
    }
    float* outR = g_kur + ((size_t)bh * 2048 + t64 * 64) * 64;
    float* outN = g_kun + ((size_t)bh * 2048 + t64 * 64) * 64;
#pragma unroll
    for (int rr = 0; rr < 4; rr++) {
        float4 oR = make_float4(ar[rr][0], ar[rr][1], ar[rr][2], ar[rr][3]);
        float4 oN = make_float4(an[rr][0], an[rr][1], an[rr][2], an[rr][3]);
        *(float4*)&outR[(size_t)(ty * 4 + rr) * 64 + tx * 4] = oR;
        *(float4*)&outN[(size_t)(ty * 4 + rr) * 64 + tx * 4] = oN;
    }
}

// ---- windowed flash attention, 64x64 tiles, 256 thr, dyn smem --------------
__global__ __launch_bounds__(256) void attn_kernel()
{
    extern __shared__ float sm[];
    float* qs = sm;                  // [d][r] stride 68
    float* ks = qs + 64 * 68;        // [d][j]
    float* vs = ks + 64 * 68;        // [j][d]
    float* ps = vs + 64 * 68;        // [j][r]
    const int qt = blockIdx.x, bh = blockIdx.y;
    const int b = bh / 12, h = bh - b * 12;
    const int tid = threadIdx.x;
    const int tx = tid & 15, ty = tid >> 4;
    const int win = g_win;

    const float* qbase = g_qkv + ((size_t)(b * 2048 + qt * 64)) * 2304 + h * 64;
#pragma unroll
    for (int q = 0; q < 4; q++) {
        int s = q * 256 + tid;
        int r = s >> 4, d0 = (s & 15) << 2;
        float4 v = *(const float4*)(qbase + (size_t)r * 2304 + d0);
        qs[(d0 + 0) * 68 + r] = v.x; qs[(d0 + 1) * 68 + r] = v.y;
        qs[(d0 + 2) * 68 + r] = v.z; qs[(d0 + 3) * 68 + r] = v.w;
    }
    float o[4][4], m[4], l[4];
#pragma unroll
    for (int i = 0; i < 4; i++) {
        m[i] = -1e30f; l[i] = 0.f;
#pragma unroll
        for (int j = 0; j < 4; j++) o[i][j] = 0.f;
    }
    int ktmax = (qt * 64 + 63 + win - 1) >> 6;
    if (ktmax > 31) ktmax = 31;

    for (int kt = qt; kt <= ktmax; kt++) {
        __syncthreads();
        const float* kb = g_qkv + ((size_t)(b * 2048 + kt * 64)) * 2304 + 768 + h * 64;
        const float* vb = kb + 768;
#pragma unroll
        for (int q = 0; q < 4; q++) {
            int s = q * 256 + tid;
            int r = s >> 4, d0 = (s & 15) << 2;
            float4 kv = *(const float4*)(kb + (size_t)r * 2304 + d0);
            ks[(d0 + 0) * 68 + r] = kv.x; ks[(d0 + 1) * 68 + r] = kv.y;
            ks[(d0 + 2) * 68 + r] = kv.z; ks[(d0 + 3) * 68 + r] = kv.w;
            *(float4*)&vs[r * 68 + d0] = *(const float4*)(vb + (size_t)r * 2304 + d0);
        }
        __syncthreads();

        float s4[4][4];
#pragma unroll
        for (int i = 0; i < 4; i++)
#pragma unroll
            for (int j = 0; j < 4; j++) s4[i][j] = 0.f;
#pragma unroll 8
        for (int d = 0; d < 64; d++) {
            float4 qv = *(float4*)&qs[d * 68 + ty * 4];
            float4 kv = *(float4*)&ks[d * 68 + tx * 4];
            s4[0][0] = fmaf(qv.x, kv.x, s4[0][0]); s4[0][1] = fmaf(qv.x, kv.y, s4[0][1]);
            s4[0][2] = fmaf(qv.x, kv.z, s4[0][2]); s4[0][3] = fmaf(qv.x, kv.w, s4[0][3]);
            s4[1][0] = fmaf(qv.y, kv.x, s4[1][0]); s4[1][1] = fmaf(qv.y, kv.y, s4[1][1]);
            s4[1][2] = fmaf(qv.y, kv.z, s4[1][2]); s4[1][3] = fmaf(qv.y, kv.w, s4[1][3]);
            s4[2][0] = fmaf(qv.z, kv.x, s4[2][0]); s4[2][1] = fmaf(qv.z, kv.y, s4[2][1]);
            s4[2][2] = fmaf(qv.z, kv.z, s4[2][2]); s4[2][3] = fmaf(qv.z, kv.w, s4[2][3]);
            s4[3][0] = fmaf(qv.w, kv.x, s4[3][0]); s4[3][1] = fmaf(qv.w, kv.y, s4[3][1]);
            s4[3][2] = fmaf(qv.w, kv.z, s4[3][2]); s4[3][3] = fmaf(qv.w, kv.w, s4[3][3]);
        }
#pragma unroll
        for (int rr = 0; rr < 4; rr++) {
            int iG = qt * 64 + ty * 4 + rr;
#pragma unroll
            for (int cc = 0; cc < 4; cc++) {
                int jG = kt * 64 + tx * 4 + cc;
                bool ok = (jG >= iG) && (jG - iG < win);
                s4[rr][cc] = ok ? s4[rr][cc] * 0.125f : -1e30f;
            }
        }
#pragma unroll
        for (int rr = 0; rr < 4; rr++) {
            float mx = fmaxf(fmaxf(s4[rr][0], s4[rr][1]), fmaxf(s4[rr][2], s4[rr][3]));
            mx = fmaxf(mx, __shfl_xor_sync(0xffffffffu, mx, 1));
            mx = fmaxf(mx, __shfl_xor_sync(0xffffffffu, mx, 2));
            mx = fmaxf(mx, __shfl_xor_sync(0xffffffffu, mx, 4));
            mx = fmaxf(mx, __shfl_xor_sync(0xffffffffu, mx, 8));
            float mnew = fmaxf(m[rr], mx);
            float corr = __expf(m[rr] - mnew);
            float rs = 0.f;
#pragma unroll
            for (int cc = 0; cc < 4; cc++) {
                s4[rr][cc] = __expf(s4[rr][cc] - mnew);
                rs += s4[rr][cc];
            }
            rs += __shfl_xor_sync(0xffffffffu, rs, 1);
            rs += __shfl_xor_sync(0xffffffffu, rs, 2);
            rs += __shfl_xor_sync(0xffffffffu, rs, 4);
            rs += __shfl_xor_sync(0xffffffffu, rs, 8);
            l[rr] = l[rr] * corr + rs;
            m[rr] = mnew;
#pragma unroll
            for (int cc = 0; cc < 4; cc++) o[rr][cc] *= corr;
        }
#pragma unroll
        for (int cc = 0; cc < 4; cc++) {
            float4 pv = make_float4(s4[0][cc], s4[1][cc], s4[2][cc], s4[3][cc]);
            *(float4*)&ps[(tx * 4 + cc) * 68 + ty * 4] = pv;
        }
        __syncthreads();
#pragma unroll 8
        for (int j = 0; j < 64; j++) {
            float4 pv = *(float4*)&ps[j * 68 + ty * 4];
            float4 vv = *(float4*)&vs[j * 68 + tx * 4];
            o[0][0] = fmaf(pv.x, vv.x, o[0][0]); o[0][1] = fmaf(pv.x, vv.y, o[0][1]);
            o[0][2] = fmaf(pv.x, vv.z, o[0][2]); o[0][3] = fmaf(pv.x, vv.w, o[0][3]);
            o[1][0] = fmaf(pv.y, vv.x, o[1][0]); o[1][1] = fmaf(pv.y, vv.y, o[1][1]);
            o[1][2] = fmaf(pv.y, vv.z, o[1][2]); o[1][3] = fmaf(pv.y, vv.w, o[1][3]);
            o[2][0] = fmaf(pv.z, vv.x, o[2][0]); o[2][1] = fmaf(pv.z, vv.y, o[2][1]);
            o[2][2] = fmaf(pv.z, vv.z, o[2][2]); o[2][3] = fmaf(pv.z, vv.w, o[2][3]);
            o[3][0] = fmaf(pv.w, vv.x, o[3][0]); o[3][1] = fmaf(pv.w, vv.y, o[3][1]);
            o[3][2] = fmaf(pv.w, vv.z, o[3][2]); o[3][3] = fmaf(pv.w, vv.w, o[3][3]);
        }
    }
    float* ob = g_local + ((size_t)bh * 2048 + qt * 64) * 64;
#pragma unroll
    for (int rr = 0; rr < 4; rr++) {
        float inv = 1.f / l[rr];
        float4 ov = make_float4(o[rr][0] * inv, o[rr][1] * inv, o[rr][2] * inv, o[rr][3] * inv);
        *(float4*)&ob[(size_t)(ty * 4 + rr) * 64 + tx * 4] = ov;
    }
}

// ---- GRU scan: one block per (b,h) -----------------------------------------
__global__ __launch_bounds__(256, 1) void gru_kernel(
    const float* __restrict__ Wr, const float* __restrict__ Wz,
    const float* __restrict__ Wn)
{
    const int bh = blockIdx.x;
    const int b = bh / 12, h = bh - b * 12;
    const int tid = threadIdx.x;
    const int j = tid >> 2, c = tid & 3;
    __shared__ float h_sh[64];
    __shared__ float rh_sh[64];

    float wr[16], wz[16], wn[16];
#pragma unroll
    for (int ii = 0; ii < 16; ii++) {
        int i = c * 16 + ii;
        wr[ii] = Wr[i * 64 + j];
        wz[ii] = Wz[i * 64 + j];
        wn[ii] = Wn[i * 64 + j];
    }
    if (tid < 64) h_sh[tid] = 0.f;
    __syncthreads();

    const float* kbase = g_qkv + ((size_t)b * 2048) * 2304 + 768 + h * 64;
    const float* vbase = kbase + 768;
    const float* kurb = g_kur + (size_t)bh * 2048 * 64;
    const float* kunb = g_kun + (size_t)bh * 2048 * 64;
    float* rout = g_rnn + (size_t)bh * 2048 * 64;

    float ktc = kbase[j], vtc = vbase[j], kurc = kurb[j], kunc = kunb[j];

    for (int t = 0; t < 2048; t++) {
        float ktn = 0.f, vtn = 0.f, kurn = 0.f, kunn = 0.f;
        if (t + 1 < 2048) {
            ktn  = kbase[(size_t)(t + 1) * 2304 + j];
            vtn  = vbase[(size_t)(t + 1) * 2304 + j];
            kurn = kurb[(size_t)(t + 1) * 64 + j];
            kunn = kunb[(size_t)(t + 1) * 64 + j];
        }
        float accR = 0.f, accZ = 0.f;
        const float4* h4 = (const float4*)&h_sh[c * 16];
#pragma unroll
        for (int q = 0; q < 4; q++) {
            float4 hv = h4[q];
            accR = fmaf(hv.x, wr[q * 4 + 0], accR); accZ = fmaf(hv.x, wz[q * 4 + 0], accZ);
            accR = fmaf(hv.y, wr[q * 4 + 1], accR); accZ = fmaf(hv.y, wz[q * 4 + 1], accZ);
            accR = fmaf(hv.z, wr[q * 4 + 2], accR); accZ = fmaf(hv.z, wz[q * 4 + 2], accZ);
            accR = fmaf(hv.w, wr[q * 4 + 3], accR); accZ = fmaf(hv.w, wz[q * 4 + 3], accZ);
        }
        accR += __shfl_xor_sync(0xffffffffu, accR, 1);
        accR += __shfl_xor_sync(0xffffffffu, accR, 2);
        accZ += __shfl_xor_sync(0xffffffffu, accZ, 1);
        accZ += __shfl_xor_sync(0xffffffffu, accZ, 2);
        float r = 1.f / (1.f + __expf(-(accR + kurc)));
        float z = 1.f / (1.f + __expf(-(accZ + ktc)));
        float hj = h_sh[j];
        if (c == 0) rh_sh[j] = r * hj;
        __syncthreads();

        float accN = 0.f;
        const float4* rh4 = (const float4*)&rh_sh[c * 16];
#pragma unroll
        for (int q = 0; q < 4; q++) {
            float4 rv = rh4[q];
            accN = fmaf(rv.x, wn[q * 4 + 0], accN);
            accN = fmaf(rv.y, wn[q * 4 + 1], accN);
            accN = fmaf(rv.z, wn[q * 4 + 2], accN);
            accN = fmaf(rv.w, wn[q * 4 + 3], accN);
        }
        accN += __shfl_xor_sync(0xffffffffu, accN, 1);
        accN += __shfl_xor_sync(0xffffffffu, accN, 2);
        float n = tanhf(accN + kunc);
        float hnew = (1.f - z) * hj + z * (n * vtc);
        if (c == 0) {
            h_sh[j] = hnew;
            rout[(size_t)t * 64 + j] = hnew;
        }
        __syncthreads();

        ktc = ktn; vtc = vtn; kurc = kurn; kunc = kunn;
    }
}

// ---- gate: alpha = sigmoid(x @ gate_w + gate_b) ----------------------------
__global__ __launch_bounds__(256) void gate_kernel(
    const float* __restrict__ x, const float* __restrict__ gw,
    const float* __restrict__ gb)
{
    int gid = blockIdx.x * 256 + threadIdx.x;
    if (gid >= 4 * 2048 * 12) return;
    int h = gid % 12;
    int bt = gid / 12;
    const float* xr = x + (size_t)bt * 768;
    float acc = gb[h];
#pragma unroll 4
    for (int i = 0; i < 768; i++)
        acc = fmaf(__ldg(xr + i), __ldg(gw + (size_t)i * 12 + h), acc);
    g_alpha[gid] = 1.f / (1.f + __expf(-acc));
}

// ---- combine: y = alpha*local + (1-alpha)*rnn, heads -> [B,T,C] ------------
__global__ __launch_bounds__(256) void combine_kernel()
{
    int gid = blockIdx.x * 256 + threadIdx.x;
    if (gid >= 4 * 2048 * 192) return;      // B*T*C/4
    int c4 = gid % 192;
    int bt = gid / 192;
    int h = c4 >> 4, d4 = c4 & 15;
    int b = bt >> 11, t = bt & 2047;
    float a = g_alpha[bt * 12 + h];
    size_t idx = ((size_t)(b * 12 + h) * 2048 + t) * 64 + d4 * 4;
    float4 lo = *(const float4*)(g_local + idx);
    float4 rn = *(const float4*)(g_rnn + idx);
    float4 o;
    o.x = a * lo.x + (1.f - a) * rn.x;
    o.y = a * lo.y + (1.f - a) * rn.y;
    o.z = a * lo.z + (1.f - a) * rn.z;
    o.w = a * lo.w + (1.f - a) * rn.w;
    *(float4*)(g_y + (size_t)bt * 768 + c4 * 4) = o;
}

extern "C" void kernel_launch(void* const* d_in, const int* in_sizes, int n_in,
                              void* d_out, int out_size) {
    const float* x      = (const float*)d_in[0];
    const void*  winp   = d_in[1];
    const float* qkv_w  = (const float*)d_in[2];
    const float* qkv_b  = (const float*)d_in[3];
    const float* proj_w = (const float*)d_in[4];
    const float* proj_b = (const float*)d_in[5];
    const float* Wr     = (const float*)d_in[6];
    const float* Ur     = (const float*)d_in[7];
    const float* Wz     = (const float*)d_in[8];
    const float* Wn     = (const float*)d_in[9];
    const float* Un     = (const float*)d_in[10];
    const float* gate_w = (const float*)d_in[11];
    const float* gate_b = (const float*)d_in[12];
    float* out = (float*)d_out;

    float* qkv_g;   cudaGetSymbolAddress((void**)&qkv_g,  g_qkv);
    float* y_g;     cudaGetSymbolAddress((void**)&y_g,    g_y);

    cudaFuncSetAttribute(attn_kernel,
        cudaFuncAttributeMaxDynamicSharedMemorySize, 4 * 64 * 68 * 4);

    win_kernel<<<1, 1>>>(winp);

    // qkv = x @ qkv_w + qkv_b : [8192,2304]
    sgemm_bias<<<dim3(18, 64), 256>>>(x, qkv_w, qkv_b, qkv_g, 8192, 2304, 768);

    // hoisted k@Ur, k@Un
    ku_kernel<<<dim3(32, 48), 256>>>(Ur, Un);

    // windowed attention
    attn_kernel<<<dim3(32, 48), 256, 4 * 64 * 68 * 4>>>();

    // recurrent scan
    gru_kernel<<<48, 256>>>(Wr, Wz, Wn);

    // gate
    gate_kernel<<<384, 256>>>(x, gate_w, gate_b);

    // mix + head-merge
    combine_kernel<<<6144, 256>>>();

    // out = y @ proj_w + proj_b : [8192,768]
    sgemm_bias<<<dim3(6, 64), 256>>>(y_g, proj_w, proj_b, out, 8192, 768, 768);
}